// round 16
// baseline (speedup 1.0000x reference)
#include <cuda_runtime.h>
#include <cuda_fp16.h>
#include <math.h>
#include <cstdint>

// Problem dims (fixed per reference)
#define Bz 64
#define Tz 512
#define Dz 2048
#define Hz 512
#define BT (Bz * Tz)          // 32768
#define NBLK 4                // H/128 h-blocks for partial scores
#define KSPL 16               // uh K-splits

// Scratch (__device__ globals; allocation-free rule)
__device__ float g_uhp[KSPL * Bz * Hz];   // uh K-split partials
__device__ float g_partial[NBLK * BT];
__device__ __half g_WaT[Hz * Dz];         // Wa transposed -> [H, D] fp16

// ---------------------------------------------------------------------------
// helpers
// ---------------------------------------------------------------------------
__device__ __forceinline__ uint32_t smem_u32(const void* p) {
    uint32_t a;
    asm("{ .reg .u64 t; cvta.to.shared.u64 t, %1; cvt.u32.u64 %0, t; }"
        : "=r"(a) : "l"(p));
    return a;
}

#define SWZ(o) ((o) ^ (((o) >> 3) & 0x70))

__device__ __forceinline__ void ldsm4(uint32_t* a, uint32_t addr) {
    asm volatile("ldmatrix.sync.aligned.m8n8.x4.shared.b16 {%0,%1,%2,%3}, [%4];"
                 : "=r"(a[0]), "=r"(a[1]), "=r"(a[2]), "=r"(a[3]) : "r"(addr));
}
// fp16 inputs, fp32 accumulate
__device__ __forceinline__ void mma16816(float* c, const uint32_t* a,
                                         const uint32_t* b) {
    asm volatile(
        "mma.sync.aligned.m16n8k16.row.col.f32.f16.f16.f32 "
        "{%0,%1,%2,%3}, {%4,%5,%6,%7}, {%8,%9}, {%0,%1,%2,%3};"
        : "+f"(c[0]), "+f"(c[1]), "+f"(c[2]), "+f"(c[3])
        : "r"(a[0]), "r"(a[1]), "r"(a[2]), "r"(a[3]), "r"(b[0]), "r"(b[1]));
}
__device__ __forceinline__ float tanh_fast(float x) {
    float y;
    asm("tanh.approx.f32 %0, %1;" : "=f"(y) : "f"(x));
    return y;
}

// ---------------------------------------------------------------------------
// Kernel 1 (fused prep):
//   blocks [0,256)    : WaT = fp16(Wa^T). Each block: 128k x 32n region
//                       = 4 x (32x32 tile); 4 independent LDG float4 rounds
//                       in flight, one sync, 4 independent 8B STGs.
//   blocks [256,512)  : uh partials, K-split 16 (128-wide slices):
//       uhp[ks][b][h] = sum_{d in slice} text[b,d]*Ua[d,h]  (+ba at ks=0)
// 256 threads per block; both jobs in one launch, fully parallel.
// ---------------------------------------------------------------------------
__global__ __launch_bounds__(256)
void prep_kernel(const float* __restrict__ Wa,
                 const float* __restrict__ text,
                 const float* __restrict__ Ua,
                 const float* __restrict__ ba,
                 __half* __restrict__ WaT,
                 float* __restrict__ uhp) {
    __shared__ float tile[4][32][33];   // 4 transpose tiles (33-pad, scalar STS)
    __shared__ float ts[8][128];        // uh text slice (whole 128-K slice)
    const int tid = threadIdx.x;

    if (blockIdx.x < 256) {
        // ---- transpose: 16 k-groups x 16 n-blocks; 4 k-tiles per block ----
        const int k0 = (blockIdx.x & 15) * 128;      // 4 tiles: k0 + 32*tt
        const int n0 = (blockIdx.x >> 4) * 32;
        const int row = tid >> 3;            // 0..31
        const int q   = tid & 7;             // 0..7 (float4 quad)

        float4 v[4];
        #pragma unroll
        for (int tt = 0; tt < 4; tt++)       // 4 independent loads in flight
            v[tt] = *(const float4*)(Wa + (size_t)(k0 + tt * 32 + row) * Hz +
                                     n0 + q * 4);
        #pragma unroll
        for (int tt = 0; tt < 4; tt++) {     // scalar STS (33-stride rows)
            tile[tt][row][q * 4 + 0] = v[tt].x;
            tile[tt][row][q * 4 + 1] = v[tt].y;
            tile[tt][row][q * 4 + 2] = v[tt].z;
            tile[tt][row][q * 4 + 3] = v[tt].w;
        }
        __syncthreads();
        #pragma unroll
        for (int tt = 0; tt < 4; tt++) {
            __half h4[4];
            #pragma unroll
            for (int i = 0; i < 4; i++)
                h4[i] = __float2half_rn(tile[tt][q * 4 + i][row]);
            *(uint2*)(WaT + (size_t)(n0 + row) * Dz + k0 + tt * 32 + q * 4) =
                *(uint2*)h4;
        }
    } else {
        // ---- uh partials: blk = hb(2) x bb(8) x ks(16) ----
        const int blk = blockIdx.x - 256;        // 0..255
        const int hb = blk & 1;
        const int bb = (blk >> 1) & 7;
        const int ks = blk >> 4;
        const int h  = hb * 256 + tid;
        const int b0 = bb * 8;
        const int d_lo = ks * (Dz / KSPL);       // 128-wide K slice
        float acc[8] = {0.f, 0.f, 0.f, 0.f, 0.f, 0.f, 0.f, 0.f};

        // load the whole 8x128 text slice once (float4 per thread; aligned)
        {
            int i = tid >> 5, c4 = (tid & 31) * 4;
            *(float4*)&ts[i][c4] =
                *(const float4*)(text + (size_t)(b0 + i) * Dz + d_lo + c4);
        }
        __syncthreads();

        #pragma unroll 16
        for (int k = 0; k < Dz / KSPL; k++) {
            float u = Ua[(size_t)(d_lo + k) * Hz + h];
            #pragma unroll
            for (int i = 0; i < 8; i++) acc[i] = fmaf(ts[i][k], u, acc[i]);
        }
        const float bav = (ks == 0) ? ba[h] : 0.f;
        float* dst = uhp + (size_t)ks * (Bz * Hz);
        #pragma unroll
        for (int i = 0; i < 8; i++) dst[(b0 + i) * Hz + h] = acc[i] + bav;
    }
}

// ---------------------------------------------------------------------------
// Kernel 2: fp16 HMMA score GEMM (fp32 acc) + fused tanh·Va epilogue.
// CTA: M=128 rows (one b), N=128 h, 8 warps as 2(M) x 4(N), warp tile 64x32.
// K=2048 in 32 chunks of 64; triple-buffered smem, one sync per chunk.
// Epilogue sums the 16 uh K-split partials when loading uh.
// ---------------------------------------------------------------------------
#define ABUF(s) ((uint32_t)(s) * 16384u)            // 3 x 16KB
#define BBUF(s) (49152u + (uint32_t)(s) * 16384u)   // 3 x 16KB
#define SM_TOTAL 98304
#define NCHUNK 32

__global__ __launch_bounds__(256, 1)
void score_hmma_kernel(const float* __restrict__ frames,
                       const __half* __restrict__ WaT,
                       const float* __restrict__ uhp,
                       const float* __restrict__ Va,
                       float* __restrict__ partial) {
    extern __shared__ char smem[];
    const uint32_t sbase = smem_u32(smem);
    const int tid = threadIdx.x;
    const int wid = tid >> 5, lane = tid & 31;
    const int warp_m = wid & 1, warp_n = wid >> 1;    // 2 x 4
    const int wm = warp_m * 64, wn = warp_n * 32;
    const int h0   = blockIdx.x * 128;
    const int row0 = blockIdx.y * 128;

    float acc[4][4][4];
    #pragma unroll
    for (int i = 0; i < 4; i++)
        #pragma unroll
        for (int j = 0; j < 4; j++)
            #pragma unroll
            for (int e = 0; e < 4; e++) acc[i][j][e] = 0.f;

    float4 pa[8], pb[4];

    // global -> regs for chunk c
    auto loadG = [&](int c) {
        const float* fA = frames + (size_t)row0 * Dz + c * 64;
        #pragma unroll
        for (int v = 0; v < 8; v++) {
            int idx = tid + v * 256;          // 128 rows x 16 float4
            int r = idx >> 4, c4 = (idx & 15) << 2;
            pa[v] = *(const float4*)(fA + (size_t)r * Dz + c4);
        }
        const __half* fB = WaT + (size_t)h0 * Dz + c * 64;
        #pragma unroll
        for (int v = 0; v < 4; v++) {
            int idx = tid + v * 256;          // 128 rows x 8 x16B
            int n = idx >> 3, k8 = (idx & 7) << 3;
            pb[v] = *(const float4*)(fB + (size_t)n * Dz + k8);
        }
    };
    // regs -> smem buffer (A converted fp32 -> fp16)
    auto storeS = [&](uint32_t aoff, uint32_t boff) {
        #pragma unroll
        for (int v = 0; v < 8; v++) {
            int idx = tid + v * 256;
            int r = idx >> 4, c4 = (idx & 15) << 2;
            __half2 p0 = __float22half2_rn(make_float2(pa[v].x, pa[v].y));
            __half2 p1 = __float22half2_rn(make_float2(pa[v].z, pa[v].w));
            uint2 pk;
            pk.x = *(uint32_t*)&p0;
            pk.y = *(uint32_t*)&p1;
            *(uint2*)(smem + aoff + SWZ((uint32_t)(r * 128 + c4 * 2))) = pk;
        }
        #pragma unroll
        for (int v = 0; v < 4; v++) {
            int idx = tid + v * 256;
            int n = idx >> 3, k8 = (idx & 7) << 3;
            *(float4*)(smem + boff + SWZ((uint32_t)(n * 128 + k8 * 2))) = pb[v];
        }
    };
    // compute on buffer (aoff, boff): 4 k16-steps
    auto compute = [&](uint32_t aoff, uint32_t boff) {
        #pragma unroll
        for (int ks = 0; ks < 4; ks++) {
            const int k16 = ks * 16;
            uint32_t bfr[4][2];
            #pragma unroll
            for (int jj = 0; jj < 2; jj++) {
                uint32_t r4[4];
                int g = lane >> 3;
                uint32_t off = (uint32_t)((wn + jj * 16 + (g >> 1) * 8 + (lane & 7)) * 128 +
                                          (k16 + (g & 1) * 8) * 2);
                ldsm4(r4, sbase + boff + SWZ(off));
                bfr[jj * 2 + 0][0] = r4[0]; bfr[jj * 2 + 0][1] = r4[1];
                bfr[jj * 2 + 1][0] = r4[2]; bfr[jj * 2 + 1][1] = r4[3];
            }
            #pragma unroll
            for (int i = 0; i < 4; i++) {
                uint32_t afr[4];
                uint32_t off = (uint32_t)((wm + i * 16 + (lane & 15)) * 128 +
                                          (k16 + (lane >> 4) * 8) * 2);
                ldsm4(afr, sbase + aoff + SWZ(off));
                #pragma unroll
                for (int j = 0; j < 4; j++)
                    mma16816(acc[i][j], afr, bfr[j]);
            }
        }
    };

    // Prologue: chunk0 -> buf0; chunk1 staged in regs
    loadG(0);
    storeS(ABUF(0), BBUF(0));
    loadG(1);

    for (int i = 0; i < NCHUNK; i++) {
        __syncthreads();   // all warps done computing chunk i-1; STS of chunk i visible
        if (i + 1 < NCHUNK) {
            const int s = (i + 1) % 3;
            storeS(ABUF(s), BBUF(s));          // regs hold chunk i+1
        }
        if (i + 2 < NCHUNK) loadG(i + 2);       // issue LDGs; land during compute
        const int s = i % 3;
        compute(ABUF(s), BBUF(s));
    }

    // ---- epilogue: tanh + Va-weighted sum over this CTA's 128 h-cols ----
    const int b = row0 >> 9;
    float va_r[8], uh_r[8];
    #pragma unroll
    for (int j = 0; j < 4; j++) {
        int col = h0 + wn + j * 8 + (lane & 3) * 2;
        va_r[j * 2 + 0] = __ldg(Va + col);
        va_r[j * 2 + 1] = __ldg(Va + col + 1);
        float u0 = 0.f, u1 = 0.f;
        #pragma unroll
        for (int p = 0; p < KSPL; p++) {
            const float* up = uhp + (size_t)p * (Bz * Hz) + b * Hz + col;
            u0 += __ldg(up);
            u1 += __ldg(up + 1);
        }
        uh_r[j * 2 + 0] = u0;
        uh_r[j * 2 + 1] = u1;
    }
    __syncthreads();
    float* red = (float*)smem;    // [128][4] overlay

    #pragma unroll
    for (int i = 0; i < 4; i++) {
        float s0 = 0.f, s1 = 0.f;
        #pragma unroll
        for (int j = 0; j < 4; j++) {
            s0 = fmaf(va_r[j*2+0], tanh_fast(acc[i][j][0] + uh_r[j*2+0]), s0);
            s0 = fmaf(va_r[j*2+1], tanh_fast(acc[i][j][1] + uh_r[j*2+1]), s0);
            s1 = fmaf(va_r[j*2+0], tanh_fast(acc[i][j][2] + uh_r[j*2+0]), s1);
            s1 = fmaf(va_r[j*2+1], tanh_fast(acc[i][j][3] + uh_r[j*2+1]), s1);
        }
        s0 += __shfl_xor_sync(0xffffffffu, s0, 1);
        s0 += __shfl_xor_sync(0xffffffffu, s0, 2);
        s1 += __shfl_xor_sync(0xffffffffu, s1, 1);
        s1 += __shfl_xor_sync(0xffffffffu, s1, 2);
        if ((lane & 3) == 0) {
            int r = wm + i * 16 + (lane >> 2);
            red[r * 4 + warp_n] = s0;
            red[(r + 8) * 4 + warp_n] = s1;
        }
    }
    __syncthreads();
    if (tid < 128) {
        float s = red[tid * 4] + red[tid * 4 + 1] +
                  red[tid * 4 + 2] + red[tid * 4 + 3];
        partial[(size_t)blockIdx.x * BT + row0 + tid] = s;
    }
}

// ---------------------------------------------------------------------------
// Kernel 3 (fused): per-CTA softmax recompute (from score partials, cheap)
// + weighted sum over frames. grid (8, B): CTA = (d-block of 256, batch b).
// ---------------------------------------------------------------------------
__global__ __launch_bounds__(256)
void out_kernel(const float* __restrict__ partial,
                const float* __restrict__ frames,
                float* __restrict__ out) {
    const int b = blockIdx.y;
    const int tid = threadIdx.x;

    __shared__ float sc[Tz];
    __shared__ float red[256];

    // scores for this b (sum of NBLK h-block partials)
    #pragma unroll
    for (int t = tid; t < Tz; t += 256) {
        float s = 0.f;
        #pragma unroll
        for (int p = 0; p < NBLK; p++)
            s += partial[(size_t)p * BT + b * Tz + t];
        sc[t] = s;
    }
    __syncthreads();

    // max reduce
    red[tid] = fmaxf(sc[tid], sc[tid + 256]);
    __syncthreads();
    for (int off = 128; off; off >>= 1) {
        if (tid < off) red[tid] = fmaxf(red[tid], red[tid + off]);
        __syncthreads();
    }
    const float m = red[0];
    __syncthreads();

    // exp + sum reduce
    float e0 = expf(sc[tid] - m);
    float e1 = expf(sc[tid + 256] - m);
    red[tid] = e0 + e1;
    __syncthreads();
    for (int off = 128; off; off >>= 1) {
        if (tid < off) red[tid] += red[tid + off];
        __syncthreads();
    }
    const float inv = 1.0f / red[0];
    sc[tid]       = e0 * inv;
    sc[tid + 256] = e1 * inv;
    __syncthreads();

    // weighted sum: out[b, d] = sum_t sc[t] * frames[b,t,d]
    const int d = blockIdx.x * 256 + tid;
    const float* fb = frames + (size_t)b * Tz * Dz + d;
    float a0 = 0.f, a1 = 0.f, a2 = 0.f, a3 = 0.f;
    float a4 = 0.f, a5 = 0.f, a6 = 0.f, a7 = 0.f;
    #pragma unroll 2
    for (int t = 0; t < Tz; t += 8) {
        a0 = fmaf(sc[t + 0], fb[(size_t)(t + 0) * Dz], a0);
        a1 = fmaf(sc[t + 1], fb[(size_t)(t + 1) * Dz], a1);
        a2 = fmaf(sc[t + 2], fb[(size_t)(t + 2) * Dz], a2);
        a3 = fmaf(sc[t + 3], fb[(size_t)(t + 3) * Dz], a3);
        a4 = fmaf(sc[t + 4], fb[(size_t)(t + 4) * Dz], a4);
        a5 = fmaf(sc[t + 5], fb[(size_t)(t + 5) * Dz], a5);
        a6 = fmaf(sc[t + 6], fb[(size_t)(t + 6) * Dz], a6);
        a7 = fmaf(sc[t + 7], fb[(size_t)(t + 7) * Dz], a7);
    }
    out[b * Dz + d] = ((a0 + a1) + (a2 + a3)) + ((a4 + a5) + (a6 + a7));
}

// ---------------------------------------------------------------------------
extern "C" void kernel_launch(void* const* d_in, const int* in_sizes, int n_in,
                              void* d_out, int out_size) {
    const float* frames = (const float*)d_in[0];
    const float* text   = (const float*)d_in[1];
    const float* Wa     = (const float*)d_in[2];
    const float* Ua     = (const float*)d_in[3];
    const float* Va     = (const float*)d_in[4];
    const float* ba     = (const float*)d_in[5];
    float* out          = (float*)d_out;

    float *uhp, *partial;
    __half* WaT;
    cudaGetSymbolAddress((void**)&uhp, g_uhp);
    cudaGetSymbolAddress((void**)&partial, g_partial);
    cudaGetSymbolAddress((void**)&WaT, g_WaT);

    cudaFuncSetAttribute(score_hmma_kernel,
                         cudaFuncAttributeMaxDynamicSharedMemorySize, SM_TOTAL);

    // 1) fused: Wa -> WaT (fp16 transpose, 4 tiles/block)  ||  uh K-splits
    prep_kernel<<<512, 256>>>(Wa, text, Ua, ba, WaT, uhp);

    // 2) HMMA score GEMM + tanh·Va epilogue (partials per h-block)
    score_hmma_kernel<<<dim3(NBLK, BT / 128), 256, SM_TOTAL>>>(
        frames, WaT, uhp, Va, partial);

    // 3) fused softmax + weighted sum
    out_kernel<<<dim3(Dz / 256, Bz), 256>>>(partial, frames, out);
}